// round 14
// baseline (speedup 1.0000x reference)
#include <cuda_runtime.h>
#include <cuda_bf16.h>
#include <stdint.h>

// GraphSAGE max-agg pipeline. R14 = R12 base + fused agg+GEMM layer kernel:
// CSR max-gather writes bf16 hi/lo planes directly into smem (chunked GEMM
// layout); pair-0 MMA reads A from smem (no global A round trip). Proj GEMM,
// LDSM inner loop, epilogue/BN, head unchanged from R12.

#define NMAX 100000
#define EMAX 1600000
#define HID 128
#define NEG 0.01f
#define GBMAX 800

#define PADC 40                        // bf16 per smem row (80 B stride)
#define CPLANE (128 * PADC * 2)        // 10240 B per plane
#define SM_GEMM_TOTAL (2048 + 4 * CPLANE)          // proj: 43008 B
#define AGGB 2048                      // fused: agg planes base
#define CBB  (2048 + 8 * CPLANE)       // fused: chunk buf base (83968)
#define SM_FUSED_TOTAL (2048 + 12 * CPLANE)        // 124928 B -> 1 CTA/SM

#define LDSM_X4(r0, r1, r2, r3, addr) \
    asm volatile("ldmatrix.sync.aligned.m8n8.x4.shared.b16 {%0,%1,%2,%3}, [%4];" \
                 : "=r"(r0), "=r"(r1), "=r"(r2), "=r"(r3) : "r"(addr))

// -------------------- device scratch ---------------------------------------
__device__ float    g_H0[NMAX * HID];
__device__ float    g_Zb[2][NMAX * HID];
__device__ uint16_t g_Wbf[7][2][128 * 128];
__device__ int   g_deg [NMAX];
__device__ int   g_off [NMAX + 1];
__device__ int   g_cur [NMAX];
__device__ int   g_srcs[EMAX];
__device__ float g_part[GBMAX * 256];
__device__ float g_statsBuf[2][256];
__device__ int   g_bsum[128];

// -------------------- helpers ----------------------------------------------
__device__ __forceinline__ float lrelu(float x) { return fmaxf(x, NEG * x); }

__device__ __forceinline__ float4 xform4(float4 v, float4 sc, float4 sh) {
    v.x = lrelu(fmaf(v.x, sc.x, sh.x));
    v.y = lrelu(fmaf(v.y, sc.y, sh.y));
    v.z = lrelu(fmaf(v.z, sc.z, sh.z));
    v.w = lrelu(fmaf(v.w, sc.w, sh.w));
    return v;
}
__device__ __forceinline__ float4 max4(float4 a, float4 b) {
    a.x = fmaxf(a.x, b.x); a.y = fmaxf(a.y, b.y);
    a.z = fmaxf(a.z, b.z); a.w = fmaxf(a.w, b.w);
    return a;
}

__device__ __forceinline__ void mma16816(float* c, const uint32_t* a,
                                         uint32_t b0, uint32_t b1) {
    asm volatile(
        "mma.sync.aligned.m16n8k16.row.col.f32.bf16.bf16.f32 "
        "{%0,%1,%2,%3}, {%4,%5,%6,%7}, {%8,%9}, {%0,%1,%2,%3};"
        : "+f"(c[0]), "+f"(c[1]), "+f"(c[2]), "+f"(c[3])
        : "r"(a[0]), "r"(a[1]), "r"(a[2]), "r"(a[3]), "r"(b0), "r"(b1));
}

__device__ __forceinline__ void split2(float2 v, uint32_t& h, uint32_t& l) {
    __nv_bfloat16 h0 = __float2bfloat16(v.x);
    __nv_bfloat16 h1 = __float2bfloat16(v.y);
    float l0 = v.x - __bfloat162float(h0);
    float l1 = v.y - __bfloat162float(h1);
    __nv_bfloat162 hp; hp.x = h0; hp.y = h1;
    __nv_bfloat162 lp; lp.x = __float2bfloat16(l0); lp.y = __float2bfloat16(l1);
    h = *(uint32_t*)&hp;
    l = *(uint32_t*)&lp;
}

// ============================ weight pre-conversion =========================
__global__ void k_cvtW(const float* w0, const float* w1, const float* w2,
                       const float* w3, const float* w4, const float* w5,
                       const float* w6) {
    const float* ws[7] = { w0, w1, w2, w3, w4, w5, w6 };
    int m = blockIdx.y;
    int p = blockIdx.x * blockDim.x + threadIdx.x;
    float2 v = *(const float2*)(ws[m] + p * 2);
    uint32_t hw, lw;
    split2(v, hw, lw);
    *(uint32_t*)&g_Wbf[m][0][p * 2] = hw;
    *(uint32_t*)&g_Wbf[m][1][p * 2] = lw;
}

// ============================ proj GEMM (R12) ===============================
// Zout := A0f @ W0^T + bias (f32 in, f32 out). M128xN128, K chunked 32.
__global__ __launch_bounds__(256, 2) void gemm_proj(
    const float* __restrict__ A0f,
    const uint16_t* __restrict__ W0p,
    const float* __restrict__ bias,
    float* __restrict__ Zout,
    int M)
{
    extern __shared__ char smem[];
    float* sbias = (float*)smem;

    uint32_t smemU = (uint32_t)__cvta_generic_to_shared(smem);
    uint32_t AhiB = smemU + 2048;
    uint32_t AloB = AhiB + CPLANE;
    uint32_t WhiB = AloB + CPLANE;
    uint32_t WloB = WhiB + CPLANE;
    char* Ahi = smem + 2048;
    char* Alo = Ahi + CPLANE;
    char* Whi = Alo + CPLANE;
    char* Wlo = Whi + CPLANE;

    int tid = threadIdx.x;
    int wid = tid >> 5;
    int lane = tid & 31;
    int m0 = blockIdx.x * 128;

    if (tid < 128) sbias[tid] = bias[tid];
    __syncthreads();

    int mw = wid & 3, nw = wid >> 2;
    int g = lane >> 2, t = lane & 3;
    int sub = lane >> 3, lr7 = lane & 7;

    int sr = tid & 127;
    int sc0 = (tid >> 7) << 4;
    int sgrow = m0 + sr;
    bool svalid = sgrow < M;
    size_t sso = ((size_t)sr * PADC + sc0) * 2;

    float acc[2][8][4];
    #pragma unroll
    for (int mt = 0; mt < 2; mt++)
        #pragma unroll
        for (int nt = 0; nt < 8; nt++)
            #pragma unroll
            for (int i = 0; i < 4; i++) acc[mt][nt][i] = 0.f;

    for (int kh = 0; kh < 4; kh++) {
        int koff = kh * 32;
        {   // stage A (convert f32)
            float a[16];
            if (svalid) {
                const float* gp = A0f + (size_t)sgrow * HID + koff + sc0;
                *(float4*)&a[0]  = *(const float4*)(gp);
                *(float4*)&a[4]  = *(const float4*)(gp + 4);
                *(float4*)&a[8]  = *(const float4*)(gp + 8);
                *(float4*)&a[12] = *(const float4*)(gp + 12);
            } else {
                #pragma unroll
                for (int i = 0; i < 16; i++) a[i] = 0.f;
            }
            uint32_t h8[8], l8[8];
            #pragma unroll
            for (int i = 0; i < 8; i++)
                split2(make_float2(a[2 * i], a[2 * i + 1]), h8[i], l8[i]);
            *(uint4*)(Ahi + sso)      = make_uint4(h8[0], h8[1], h8[2], h8[3]);
            *(uint4*)(Ahi + sso + 16) = make_uint4(h8[4], h8[5], h8[6], h8[7]);
            *(uint4*)(Alo + sso)      = make_uint4(l8[0], l8[1], l8[2], l8[3]);
            *(uint4*)(Alo + sso + 16) = make_uint4(l8[4], l8[5], l8[6], l8[7]);
        }
        {   // stage W (copies)
            const uint16_t* hp = W0p + (size_t)sr * HID + koff + sc0;
            const uint16_t* lp = hp + 16384;
            *(uint4*)(Whi + sso)      = *(const uint4*)hp;
            *(uint4*)(Whi + sso + 16) = *(const uint4*)(hp + 8);
            *(uint4*)(Wlo + sso)      = *(const uint4*)lp;
            *(uint4*)(Wlo + sso + 16) = *(const uint4*)(lp + 8);
        }
        __syncthreads();

        #pragma unroll
        for (int ks = 0; ks < 2; ks++) {
            int k0 = ks * 16;
            uint32_t ah[2][4], al[2][4];
            #pragma unroll
            for (int mt = 0; mt < 2; mt++) {
                uint32_t off = (uint32_t)(((mw * 32 + mt * 16 + (sub & 1) * 8 + lr7) * PADC)
                                          + k0 + (sub >> 1) * 8) * 2;
                LDSM_X4(ah[mt][0], ah[mt][1], ah[mt][2], ah[mt][3], AhiB + off);
                LDSM_X4(al[mt][0], al[mt][1], al[mt][2], al[mt][3], AloB + off);
            }
            uint32_t bh[8][2], bl[8][2];
            #pragma unroll
            for (int p = 0; p < 4; p++) {
                uint32_t off = (uint32_t)(((nw * 64 + p * 16 + (sub >> 1) * 8 + lr7) * PADC)
                                          + k0 + (sub & 1) * 8) * 2;
                LDSM_X4(bh[2 * p][0], bh[2 * p][1], bh[2 * p + 1][0], bh[2 * p + 1][1],
                        WhiB + off);
                LDSM_X4(bl[2 * p][0], bl[2 * p][1], bl[2 * p + 1][0], bl[2 * p + 1][1],
                        WloB + off);
            }
            #pragma unroll
            for (int nt = 0; nt < 8; nt++)
                #pragma unroll
                for (int mt = 0; mt < 2; mt++) {
                    mma16816(acc[mt][nt], ah[mt], bh[nt][0], bh[nt][1]);
                    mma16816(acc[mt][nt], al[mt], bh[nt][0], bh[nt][1]);
                    mma16816(acc[mt][nt], ah[mt], bl[nt][0], bl[nt][1]);
                }
        }
        __syncthreads();
    }

    #pragma unroll
    for (int nt = 0; nt < 8; nt++) {
        int col = nw * 64 + nt * 8 + t * 2;
        float b0v = sbias[col], b1v = sbias[col + 1];
        #pragma unroll
        for (int mt = 0; mt < 2; mt++) {
            int gm = m0 + mw * 32 + mt * 16 + g;
            if (gm < M)
                *(float2*)&Zout[(size_t)gm * HID + col] =
                    make_float2(acc[mt][nt][0] + b0v, acc[mt][nt][1] + b1v);
            if (gm + 8 < M)
                *(float2*)&Zout[(size_t)(gm + 8) * HID + col] =
                    make_float2(acc[mt][nt][2] + b0v, acc[mt][nt][3] + b1v);
        }
    }
}

// ============================ fused agg + layer GEMM ========================
// Phase A: A = max-agg(xform(Hin)) -> smem planes (chunk layout).
// Phase B: Z = A @ Wl^T + xform(Hin) @ Wr^T + bias ; BN partials.
__global__ __launch_bounds__(256, 1) void gemm_fused(
    const float* __restrict__ Hin,
    const float* __restrict__ prevStats,
    const uint16_t* __restrict__ Wlp,    // hi +0, lo +16384
    const uint16_t* __restrict__ Wrp,
    const float* __restrict__ bias,
    float* __restrict__ Zout,
    float* __restrict__ part,
    int M, int hasStats)
{
    extern __shared__ char smem[];
    float* sstats = (float*)smem;             // 256 floats
    float* sbias  = (float*)(smem + 1024);    // 128 floats
    float* scr    = (float*)(smem + AGGB);    // aliases agg planes (epilogue)

    uint32_t smemU = (uint32_t)__cvta_generic_to_shared(smem);
    char* cb = smem + CBB;
    char* A1hi = cb;                 // pair-1 staging chunk buf
    char* A1lo = cb + CPLANE;
    char* Whi  = cb + 2 * CPLANE;
    char* Wlo  = cb + 3 * CPLANE;
    uint32_t A1hiB = smemU + CBB;
    uint32_t A1loB = A1hiB + CPLANE;
    uint32_t WhiB  = A1hiB + 2 * CPLANE;
    uint32_t WloB  = A1hiB + 3 * CPLANE;

    int tid = threadIdx.x;
    int wid = tid >> 5;
    int lane = tid & 31;
    int m0 = blockIdx.x * 128;

    if (tid < 128) sbias[tid] = bias[tid];
    if (hasStats && tid < 256) sstats[tid] = prevStats[tid];
    __syncthreads();

    // ---- Phase A: aggregation into smem planes (warp per node, 16 nodes/warp)
    {
        float4 sc, sh;
        if (hasStats) {
            sc = *(const float4*)&sstats[lane * 4];
            sh = *(const float4*)&sstats[128 + lane * 4];
        }
        int chunk = lane >> 3;
        int cc = (lane * 4) & 31;
        uint32_t hibase = AGGB + (uint32_t)chunk * 2 * CPLANE;

        for (int i = 0; i < 16; i++) {
            int nloc = wid * 16 + i;
            int n = m0 + nloc;
            float4 m = make_float4(0.f, 0.f, 0.f, 0.f);
            if (n < M) {
                int s = g_off[n], e = g_off[n + 1];
                m = make_float4(-3.4e38f, -3.4e38f, -3.4e38f, -3.4e38f);
                int j = s;
                for (; j + 4 <= e; j += 4) {
                    int s0 = g_srcs[j], s1 = g_srcs[j + 1];
                    int s2 = g_srcs[j + 2], s3 = g_srcs[j + 3];
                    float4 v0 = *(const float4*)&Hin[(size_t)s0 * HID + lane * 4];
                    float4 v1 = *(const float4*)&Hin[(size_t)s1 * HID + lane * 4];
                    float4 v2 = *(const float4*)&Hin[(size_t)s2 * HID + lane * 4];
                    float4 v3 = *(const float4*)&Hin[(size_t)s3 * HID + lane * 4];
                    if (hasStats) {
                        v0 = xform4(v0, sc, sh); v1 = xform4(v1, sc, sh);
                        v2 = xform4(v2, sc, sh); v3 = xform4(v3, sc, sh);
                    }
                    m = max4(m, max4(max4(v0, v1), max4(v2, v3)));
                }
                for (; j < e; ++j) {
                    float4 v = *(const float4*)&Hin[(size_t)g_srcs[j] * HID + lane * 4];
                    if (hasStats) v = xform4(v, sc, sh);
                    m = max4(m, v);
                }
                if (e == s) m = make_float4(0.f, 0.f, 0.f, 0.f);
            }
            uint32_t h0, l0, h1, l1;
            split2(make_float2(m.x, m.y), h0, l0);
            split2(make_float2(m.z, m.w), h1, l1);
            uint32_t off = (uint32_t)(nloc * PADC + cc) * 2;
            *(uint2*)(smem + hibase + off) = make_uint2(h0, h1);
            *(uint2*)(smem + hibase + CPLANE + off) = make_uint2(l0, l1);
        }
    }
    __syncthreads();

    int mw = wid & 3, nw = wid >> 2;
    int g = lane >> 2, t = lane & 3;
    int sub = lane >> 3, lr7 = lane & 7;

    int sr = tid & 127;
    int sc0 = (tid >> 7) << 4;
    int sgrow = m0 + sr;
    bool svalid = sgrow < M;
    size_t sso = ((size_t)sr * PADC + sc0) * 2;

    float acc[2][8][4];
    #pragma unroll
    for (int mt = 0; mt < 2; mt++)
        #pragma unroll
        for (int nt = 0; nt < 8; nt++)
            #pragma unroll
            for (int i = 0; i < 4; i++) acc[mt][nt][i] = 0.f;

    // ---- pair 0: A(agg, in smem) @ Wl^T
    for (int kh = 0; kh < 4; kh++) {
        int koff = kh * 32;
        {   // stage W chunk only
            const uint16_t* hp = Wlp + (size_t)sr * HID + koff + sc0;
            const uint16_t* lp = hp + 16384;
            *(uint4*)(Whi + sso)      = *(const uint4*)hp;
            *(uint4*)(Whi + sso + 16) = *(const uint4*)(hp + 8);
            *(uint4*)(Wlo + sso)      = *(const uint4*)lp;
            *(uint4*)(Wlo + sso + 16) = *(const uint4*)(lp + 8);
        }
        __syncthreads();

        uint32_t AhiB = smemU + AGGB + (uint32_t)kh * 2 * CPLANE;
        uint32_t AloB = AhiB + CPLANE;

        #pragma unroll
        for (int ks = 0; ks < 2; ks++) {
            int k0 = ks * 16;
            uint32_t ah[2][4], al[2][4];
            #pragma unroll
            for (int mt = 0; mt < 2; mt++) {
                uint32_t off = (uint32_t)(((mw * 32 + mt * 16 + (sub & 1) * 8 + lr7) * PADC)
                                          + k0 + (sub >> 1) * 8) * 2;
                LDSM_X4(ah[mt][0], ah[mt][1], ah[mt][2], ah[mt][3], AhiB + off);
                LDSM_X4(al[mt][0], al[mt][1], al[mt][2], al[mt][3], AloB + off);
            }
            uint32_t bh[8][2], bl[8][2];
            #pragma unroll
            for (int p = 0; p < 4; p++) {
                uint32_t off = (uint32_t)(((nw * 64 + p * 16 + (sub >> 1) * 8 + lr7) * PADC)
                                          + k0 + (sub & 1) * 8) * 2;
                LDSM_X4(bh[2 * p][0], bh[2 * p][1], bh[2 * p + 1][0], bh[2 * p + 1][1],
                        WhiB + off);
                LDSM_X4(bl[2 * p][0], bl[2 * p][1], bl[2 * p + 1][0], bl[2 * p + 1][1],
                        WloB + off);
            }
            #pragma unroll
            for (int nt = 0; nt < 8; nt++)
                #pragma unroll
                for (int mt = 0; mt < 2; mt++) {
                    mma16816(acc[mt][nt], ah[mt], bh[nt][0], bh[nt][1]);
                    mma16816(acc[mt][nt], al[mt], bh[nt][0], bh[nt][1]);
                    mma16816(acc[mt][nt], ah[mt], bl[nt][0], bl[nt][1]);
                }
        }
        __syncthreads();
    }

    // ---- pair 1: xform(Hin) @ Wr^T (conversion staging)
    for (int kh = 0; kh < 4; kh++) {
        int koff = kh * 32;
        {   // stage A1 (convert + xform)
            float a[16];
            if (svalid) {
                const float* gp = Hin + (size_t)sgrow * HID + koff + sc0;
                *(float4*)&a[0]  = *(const float4*)(gp);
                *(float4*)&a[4]  = *(const float4*)(gp + 4);
                *(float4*)&a[8]  = *(const float4*)(gp + 8);
                *(float4*)&a[12] = *(const float4*)(gp + 12);
            } else {
                #pragma unroll
                for (int i = 0; i < 16; i++) a[i] = 0.f;
            }
            if (hasStats) {
                int kb = koff + sc0;
                #pragma unroll
                for (int i = 0; i < 16; i++)
                    a[i] = lrelu(fmaf(a[i], sstats[kb + i], sstats[128 + kb + i]));
            }
            uint32_t h8[8], l8[8];
            #pragma unroll
            for (int i = 0; i < 8; i++)
                split2(make_float2(a[2 * i], a[2 * i + 1]), h8[i], l8[i]);
            *(uint4*)(A1hi + sso)      = make_uint4(h8[0], h8[1], h8[2], h8[3]);
            *(uint4*)(A1hi + sso + 16) = make_uint4(h8[4], h8[5], h8[6], h8[7]);
            *(uint4*)(A1lo + sso)      = make_uint4(l8[0], l8[1], l8[2], l8[3]);
            *(uint4*)(A1lo + sso + 16) = make_uint4(l8[4], l8[5], l8[6], l8[7]);
        }
        {   // stage W chunk
            const uint16_t* hp = Wrp + (size_t)sr * HID + koff + sc0;
            const uint16_t* lp = hp + 16384;
            *(uint4*)(Whi + sso)      = *(const uint4*)hp;
            *(uint4*)(Whi + sso + 16) = *(const uint4*)(hp + 8);
            *(uint4*)(Wlo + sso)      = *(const uint4*)lp;
            *(uint4*)(Wlo + sso + 16) = *(const uint4*)(lp + 8);
        }
        __syncthreads();

        #pragma unroll
        for (int ks = 0; ks < 2; ks++) {
            int k0 = ks * 16;
            uint32_t ah[2][4], al[2][4];
            #pragma unroll
            for (int mt = 0; mt < 2; mt++) {
                uint32_t off = (uint32_t)(((mw * 32 + mt * 16 + (sub & 1) * 8 + lr7) * PADC)
                                          + k0 + (sub >> 1) * 8) * 2;
                LDSM_X4(ah[mt][0], ah[mt][1], ah[mt][2], ah[mt][3], A1hiB + off);
                LDSM_X4(al[mt][0], al[mt][1], al[mt][2], al[mt][3], A1loB + off);
            }
            uint32_t bh[8][2], bl[8][2];
            #pragma unroll
            for (int p = 0; p < 4; p++) {
                uint32_t off = (uint32_t)(((nw * 64 + p * 16 + (sub >> 1) * 8 + lr7) * PADC)
                                          + k0 + (sub & 1) * 8) * 2;
                LDSM_X4(bh[2 * p][0], bh[2 * p][1], bh[2 * p + 1][0], bh[2 * p + 1][1],
                        WhiB + off);
                LDSM_X4(bl[2 * p][0], bl[2 * p][1], bl[2 * p + 1][0], bl[2 * p + 1][1],
                        WloB + off);
            }
            #pragma unroll
            for (int nt = 0; nt < 8; nt++)
                #pragma unroll
                for (int mt = 0; mt < 2; mt++) {
                    mma16816(acc[mt][nt], ah[mt], bh[nt][0], bh[nt][1]);
                    mma16816(acc[mt][nt], al[mt], bh[nt][0], bh[nt][1]);
                    mma16816(acc[mt][nt], ah[mt], bl[nt][0], bl[nt][1]);
                }
        }
        __syncthreads();
    }

    // ---- epilogue: stores + BN column partials
    #pragma unroll
    for (int nt = 0; nt < 8; nt++) {
        int col = nw * 64 + nt * 8 + t * 2;
        float b0v = sbias[col], b1v = sbias[col + 1];
        float s0 = 0.f, s1 = 0.f, q0 = 0.f, q1 = 0.f;
        #pragma unroll
        for (int mt = 0; mt < 2; mt++) {
            int gm = m0 + mw * 32 + mt * 16 + g;
            float v00 = acc[mt][nt][0] + b0v;
            float v01 = acc[mt][nt][1] + b1v;
            float v10 = acc[mt][nt][2] + b0v;
            float v11 = acc[mt][nt][3] + b1v;
            if (gm < M) {
                *(float2*)&Zout[(size_t)gm * HID + col] = make_float2(v00, v01);
                s0 += v00; s1 += v01; q0 += v00 * v00; q1 += v01 * v01;
            }
            if (gm + 8 < M) {
                *(float2*)&Zout[(size_t)(gm + 8) * HID + col] = make_float2(v10, v11);
                s0 += v10; s1 += v11; q0 += v10 * v10; q1 += v11 * v11;
            }
        }
        #pragma unroll
        for (int o = 16; o >= 4; o >>= 1) {
            s0 += __shfl_down_sync(0xffffffffu, s0, o);
            s1 += __shfl_down_sync(0xffffffffu, s1, o);
            q0 += __shfl_down_sync(0xffffffffu, q0, o);
            q1 += __shfl_down_sync(0xffffffffu, q1, o);
        }
        if (lane < 4) {
            int c = nw * 64 + nt * 8 + lane * 2;
            scr[mw * 128 + c] = s0;
            scr[mw * 128 + c + 1] = s1;
            scr[512 + mw * 128 + c] = q0;
            scr[512 + mw * 128 + c + 1] = q1;
        }
    }
    __syncthreads();
    if (tid < 128) {
        float s = scr[tid] + scr[128 + tid] + scr[256 + tid] + scr[384 + tid];
        float q = scr[512 + tid] + scr[640 + tid] + scr[768 + tid] + scr[896 + tid];
        part[blockIdx.x * 256 + tid] = s;
        part[blockIdx.x * 256 + 128 + tid] = q;
    }
}

// ============================ CSR construction ==============================
__global__ void k_count(const int* __restrict__ dst, int E) {
    int e = blockIdx.x * blockDim.x + threadIdx.x;
    if (e < E) atomicAdd(&g_deg[dst[e]], 1);
}

__global__ void k_scanA(int M) {
    __shared__ int sh[1024];
    int i = blockIdx.x * 1024 + threadIdx.x;
    int v = (i < M) ? g_deg[i] : 0;
    sh[threadIdx.x] = v;
    __syncthreads();
    #pragma unroll
    for (int d = 1; d < 1024; d <<= 1) {
        int tt = (threadIdx.x >= d) ? sh[threadIdx.x - d] : 0;
        __syncthreads();
        sh[threadIdx.x] += tt;
        __syncthreads();
    }
    if (i < M) g_off[i + 1] = sh[threadIdx.x];
    if (threadIdx.x == 1023) g_bsum[blockIdx.x] = sh[1023];
}

__global__ void k_scanB(int nb) {
    int t = threadIdx.x;
    int orig = (t < nb) ? g_bsum[t] : 0;
    int v = orig;
    #pragma unroll
    for (int o = 1; o < 32; o <<= 1) {
        int u = __shfl_up_sync(0xffffffffu, v, o);
        if ((t & 31) >= o) v += u;
    }
    __shared__ int ws[4];
    if ((t & 31) == 31) ws[t >> 5] = v;
    __syncthreads();
    int add = 0;
    #pragma unroll
    for (int w = 0; w < 4; w++) add += (w < (t >> 5)) ? ws[w] : 0;
    v += add;
    if (t < nb) g_bsum[t] = v - orig;
}

__global__ void k_scanC(int M) {
    int i = blockIdx.x * blockDim.x + threadIdx.x;
    if (i < M) {
        int inc = g_off[i + 1] + g_bsum[i >> 10];
        g_off[i + 1] = inc;
        g_cur[i] = inc - g_deg[i];
        if (i == 0) g_off[0] = 0;
    }
}

__global__ void k_scatter(const int* __restrict__ src, const int* __restrict__ dst, int E) {
    int e = blockIdx.x * blockDim.x + threadIdx.x;
    if (e < E) {
        int pos = atomicAdd(&g_cur[dst[e]], 1);
        g_srcs[pos] = src[e];
    }
}

// ============================ BN stats finalize =============================
__global__ __launch_bounds__(1024) void k_bnfinal(
    const float* __restrict__ g, const float* __restrict__ be,
    float* __restrict__ statsOut, int M, int NB)
{
    __shared__ double sD[8][128];
    __shared__ double qD[8][128];
    int tid = threadIdx.x;
    int grp = tid >> 7;
    int c = tid & 127;
    double s = 0.0, q = 0.0;
    for (int b = grp; b < NB; b += 8) {
        s += (double)g_part[b * 256 + c];
        q += (double)g_part[b * 256 + 128 + c];
    }
    sD[grp][c] = s; qD[grp][c] = q;
    __syncthreads();
    if (tid < 128) {
        double ss = 0.0, qq = 0.0;
        #pragma unroll
        for (int gg = 0; gg < 8; gg++) { ss += sD[gg][tid]; qq += qD[gg][tid]; }
        double mean = ss / (double)M;
        double var = qq / (double)M - mean * mean;
        float rstd = (float)(1.0 / sqrt(var + 1e-5));
        float scale = g[tid] * rstd;
        statsOut[tid] = scale;
        statsOut[128 + tid] = be[tid] - (float)mean * scale;
    }
}

// ============================ head (warp per row) ===========================
__global__ __launch_bounds__(256) void k_fc(
    const float* __restrict__ Zlast, const float* __restrict__ stats,
    const float* __restrict__ W1, const float* __restrict__ b1,
    const float* __restrict__ W2, const float* __restrict__ b2,
    float* __restrict__ out, int M)
{
    __shared__ float W1s[64][132];
    __shared__ float b1s[64], w2s[64];
    __shared__ float xsh[8][128];

    int tid = threadIdx.x;
    int wid = tid >> 5;
    int lane = tid & 31;

    for (int i = tid; i < 64 * 128; i += 256) W1s[i >> 7][i & 127] = W1[i];
    if (tid < 64) { b1s[tid] = b1[tid]; w2s[tid] = W2[tid]; }
    __syncthreads();

    float4 sc = *(const float4*)&stats[lane * 4];
    float4 sh = *(const float4*)&stats[128 + lane * 4];
    float bias2 = b2[0];
    float w2a = w2s[lane], w2b = w2s[lane + 32];
    float b1a = b1s[lane], b1b = b1s[lane + 32];

    const int ROWS = 8;
    int rbase = blockIdx.x * (8 * ROWS) + wid * ROWS;

    for (int rr = 0; rr < ROWS; rr++) {
        int r = rbase + rr;
        if (r >= M) return;
        float4 z = *(const float4*)&Zlast[(size_t)r * HID + lane * 4];
        float4 h = *(const float4*)&g_H0[(size_t)r * HID + lane * 4];
        z = xform4(z, sc, sh);
        z.x += h.x; z.y += h.y; z.z += h.z; z.w += h.w;
        *(float4*)&xsh[wid][lane * 4] = z;
        __syncwarp();

        float acc0 = 0.f, acc1 = 0.f;
        #pragma unroll
        for (int k = 0; k < 128; k += 4) {
            float4 xv = *(const float4*)&xsh[wid][k];
            float4 w0 = *(const float4*)&W1s[lane][k];
            float4 w1 = *(const float4*)&W1s[lane + 32][k];
            acc0 = fmaf(xv.x, w0.x, acc0); acc0 = fmaf(xv.y, w0.y, acc0);
            acc0 = fmaf(xv.z, w0.z, acc0); acc0 = fmaf(xv.w, w0.w, acc0);
            acc1 = fmaf(xv.x, w1.x, acc1); acc1 = fmaf(xv.y, w1.y, acc1);
            acc1 = fmaf(xv.z, w1.z, acc1); acc1 = fmaf(xv.w, w1.w, acc1);
        }
        float f0 = lrelu(acc0 + b1a);
        float f1 = lrelu(acc1 + b1b);
        float contrib = f0 * w2a + f1 * w2b;
        #pragma unroll
        for (int o = 16; o > 0; o >>= 1)
            contrib += __shfl_down_sync(0xffffffffu, contrib, o);
        if (lane == 0) out[r] = contrib + bias2;
        __syncwarp();
    }
}

// ============================ launch ========================================
extern "C" void kernel_launch(void* const* d_in, const int* in_sizes, int n_in,
                              void* d_out, int out_size)
{
    const float* x    = (const float*)d_in[0];
    const int*   ei   = (const int*)d_in[1];
    const float* W_in = (const float*)d_in[2];
    const float* b_in = (const float*)d_in[3];
    const float* Wl[3] = { (const float*)d_in[4], (const float*)d_in[7], (const float*)d_in[10] };
    const float* bl[3] = { (const float*)d_in[5], (const float*)d_in[8], (const float*)d_in[11] };
    const float* Wr[3] = { (const float*)d_in[6], (const float*)d_in[9], (const float*)d_in[12] };
    const float* gm[3] = { (const float*)d_in[13], (const float*)d_in[15], (const float*)d_in[17] };
    const float* be[3] = { (const float*)d_in[14], (const float*)d_in[16], (const float*)d_in[18] };
    const float* W_fc1 = (const float*)d_in[19];
    const float* b_fc1 = (const float*)d_in[20];
    const float* W_fc2 = (const float*)d_in[21];
    const float* b_fc2 = (const float*)d_in[22];
    float* out = (float*)d_out;

    int M = in_sizes[0] / HID;
    int E = in_sizes[1] / 2;
    const int* src = ei;
    const int* dst = ei + E;

    cudaFuncSetAttribute(gemm_proj, cudaFuncAttributeMaxDynamicSharedMemorySize,
                         SM_GEMM_TOTAL);
    cudaFuncSetAttribute(gemm_fused, cudaFuncAttributeMaxDynamicSharedMemorySize,
                         SM_FUSED_TOTAL);

    void *pH0v, *pZv, *pPartv, *pStatsv, *pDegv, *pWv;
    cudaGetSymbolAddress(&pH0v, g_H0);
    cudaGetSymbolAddress(&pZv, g_Zb);
    cudaGetSymbolAddress(&pPartv, g_part);
    cudaGetSymbolAddress(&pStatsv, g_statsBuf);
    cudaGetSymbolAddress(&pDegv, g_deg);
    cudaGetSymbolAddress(&pWv, g_Wbf);
    float* pH0 = (float*)pH0v;
    float* pZ0 = (float*)pZv;
    float* pZ1 = pZ0 + (size_t)NMAX * HID;
    float* pPart = (float*)pPartv;
    float* pStats0 = (float*)pStatsv;
    float* pStats1 = pStats0 + 256;
    uint16_t* pW  = (uint16_t*)pWv;
    uint16_t* pWm[7];
    for (int i = 0; i < 7; i++) pWm[i] = pW + (size_t)i * 2 * 16384;

    int scanBlocks = (M + 1023) / 1024;
    int gemmGrid = (M + 127) / 128;

    // ---- setup + CSR build; proj GEMM is the 4th launch (ncu target)
    cudaMemsetAsync(pDegv, 0, (size_t)M * sizeof(int));
    k_cvtW<<<dim3(32, 7), 256>>>(W_in, Wl[0], Wr[0], Wl[1], Wr[1], Wl[2], Wr[2]); // 1
    k_count<<<(E + 511) / 512, 512>>>(dst, E);                                     // 2
    k_scanA<<<scanBlocks, 1024>>>(M);                                              // 3
    gemm_proj<<<gemmGrid, 256, SM_GEMM_TOTAL>>>(x, pWm[0], b_in, pH0, M);          // 4 (profiled)
    k_scanB<<<1, 128>>>(scanBlocks);
    k_scanC<<<(M + 255) / 256, 256>>>(M);
    k_scatter<<<(E + 511) / 512, 512>>>(src, dst, E);

    // ---- layer 1 (input H0, no xform)
    gemm_fused<<<gemmGrid, 256, SM_FUSED_TOTAL>>>(pH0, nullptr, pWm[1], pWm[2],
                                                  bl[0], pZ0, pPart, M, 0);
    k_bnfinal<<<1, 1024>>>(gm[0], be[0], pStats0, M, gemmGrid);

    // ---- layer 2
    gemm_fused<<<gemmGrid, 256, SM_FUSED_TOTAL>>>(pZ0, pStats0, pWm[3], pWm[4],
                                                  bl[1], pZ1, pPart, M, 1);
    k_bnfinal<<<1, 1024>>>(gm[1], be[1], pStats1, M, gemmGrid);

    // ---- layer 3
    gemm_fused<<<gemmGrid, 256, SM_FUSED_TOTAL>>>(pZ1, pStats1, pWm[5], pWm[6],
                                                  bl[2], pZ0, pPart, M, 1);
    k_bnfinal<<<1, 1024>>>(gm[2], be[2], pStats0, M, gemmGrid);

    // ---- head
    k_fc<<<(M + 63) / 64, 256>>>(pZ0, pStats0, W_fc1, b_fc1, W_fc2, b_fc2, out, M);
}

// round 15
// speedup vs baseline: 1.3501x; 1.3501x over previous
#include <cuda_runtime.h>
#include <cuda_bf16.h>
#include <stdint.h>

// GraphSAGE max-agg pipeline. R15 = R12 pipeline (best) with specialized GEMM
// kernels: gemm_proj (f32 A convert) and gemm_layer (pair0 plane copies,
// pair1 f32+xform convert), no runtime operand branches. LDSM + HMMA,
// K chunked 32, 42KB smem, 2 CTAs/SM.

#define NMAX 100000
#define EMAX 1600000
#define HID 128
#define NEG 0.01f
#define GBMAX 800

#define PADC 40
#define CPLANE (128 * PADC * 2)
#define SM_GEMM_TOTAL (2048 + 4 * CPLANE)   // 43008 B -> 2 CTAs/SM

#define LDSM_X4(r0, r1, r2, r3, addr) \
    asm volatile("ldmatrix.sync.aligned.m8n8.x4.shared.b16 {%0,%1,%2,%3}, [%4];" \
                 : "=r"(r0), "=r"(r1), "=r"(r2), "=r"(r3) : "r"(addr))

// -------------------- device scratch ---------------------------------------
__device__ float    g_H0[NMAX * HID];
__device__ float    g_Zb[2][NMAX * HID];
__device__ uint16_t g_AbfHi[NMAX * HID];
__device__ uint16_t g_AbfLo[NMAX * HID];
__device__ uint16_t g_Wbf[7][2][128 * 128];
__device__ int   g_deg [NMAX];
__device__ int   g_off [NMAX + 1];
__device__ int   g_cur [NMAX];
__device__ int   g_srcs[EMAX];
__device__ float g_part[GBMAX * 256];
__device__ float g_statsBuf[2][256];
__device__ int   g_bsum[128];

// -------------------- helpers ----------------------------------------------
__device__ __forceinline__ float lrelu(float x) { return fmaxf(x, NEG * x); }

__device__ __forceinline__ float4 xform4(float4 v, float4 sc, float4 sh) {
    v.x = lrelu(fmaf(v.x, sc.x, sh.x));
    v.y = lrelu(fmaf(v.y, sc.y, sh.y));
    v.z = lrelu(fmaf(v.z, sc.z, sh.z));
    v.w = lrelu(fmaf(v.w, sc.w, sh.w));
    return v;
}
__device__ __forceinline__ float4 max4(float4 a, float4 b) {
    a.x = fmaxf(a.x, b.x); a.y = fmaxf(a.y, b.y);
    a.z = fmaxf(a.z, b.z); a.w = fmaxf(a.w, b.w);
    return a;
}

__device__ __forceinline__ void mma16816(float* c, const uint32_t* a,
                                         uint32_t b0, uint32_t b1) {
    asm volatile(
        "mma.sync.aligned.m16n8k16.row.col.f32.bf16.bf16.f32 "
        "{%0,%1,%2,%3}, {%4,%5,%6,%7}, {%8,%9}, {%0,%1,%2,%3};"
        : "+f"(c[0]), "+f"(c[1]), "+f"(c[2]), "+f"(c[3])
        : "r"(a[0]), "r"(a[1]), "r"(a[2]), "r"(a[3]), "r"(b0), "r"(b1));
}

__device__ __forceinline__ void split2(float2 v, uint32_t& h, uint32_t& l) {
    __nv_bfloat16 h0 = __float2bfloat16(v.x);
    __nv_bfloat16 h1 = __float2bfloat16(v.y);
    float l0 = v.x - __bfloat162float(h0);
    float l1 = v.y - __bfloat162float(h1);
    __nv_bfloat162 hp; hp.x = h0; hp.y = h1;
    __nv_bfloat162 lp; lp.x = __float2bfloat16(l0); lp.y = __float2bfloat16(l1);
    h = *(uint32_t*)&hp;
    l = *(uint32_t*)&lp;
}

// inner-loop compute macro shared by both GEMMs (reads smem plane bases)
#define GEMM_CHUNK_COMPUTE(AhiB, AloB, WhiB, WloB)                             \
    _Pragma("unroll")                                                          \
    for (int ks = 0; ks < 2; ks++) {                                           \
        int k0 = ks * 16;                                                      \
        uint32_t ah[2][4], al[2][4];                                           \
        _Pragma("unroll")                                                      \
        for (int mt = 0; mt < 2; mt++) {                                       \
            uint32_t off = (uint32_t)(((mw * 32 + mt * 16 + (sub & 1) * 8 + lr7) * PADC) \
                                      + k0 + (sub >> 1) * 8) * 2;              \
            LDSM_X4(ah[mt][0], ah[mt][1], ah[mt][2], ah[mt][3], (AhiB) + off); \
            LDSM_X4(al[mt][0], al[mt][1], al[mt][2], al[mt][3], (AloB) + off); \
        }                                                                      \
        uint32_t bh[8][2], bl[8][2];                                           \
        _Pragma("unroll")                                                      \
        for (int p = 0; p < 4; p++) {                                          \
            uint32_t off = (uint32_t)(((nw * 64 + p * 16 + (sub >> 1) * 8 + lr7) * PADC) \
                                      + k0 + (sub & 1) * 8) * 2;               \
            LDSM_X4(bh[2 * p][0], bh[2 * p][1], bh[2 * p + 1][0], bh[2 * p + 1][1], \
                    (WhiB) + off);                                             \
            LDSM_X4(bl[2 * p][0], bl[2 * p][1], bl[2 * p + 1][0], bl[2 * p + 1][1], \
                    (WloB) + off);                                             \
        }                                                                      \
        _Pragma("unroll")                                                      \
        for (int nt = 0; nt < 8; nt++)                                         \
            _Pragma("unroll")                                                  \
            for (int mt = 0; mt < 2; mt++) {                                   \
                mma16816(acc[mt][nt], ah[mt], bh[nt][0], bh[nt][1]);           \
                mma16816(acc[mt][nt], al[mt], bh[nt][0], bh[nt][1]);           \
                mma16816(acc[mt][nt], ah[mt], bl[nt][0], bl[nt][1]);           \
            }                                                                  \
    }

#define STAGE_W_CHUNK(Wp)                                                      \
    {                                                                          \
        const uint16_t* hp = (Wp) + (size_t)sr * HID + koff + sc0;             \
        const uint16_t* lp = hp + 16384;                                       \
        *(uint4*)(Whi + sso)      = *(const uint4*)hp;                         \
        *(uint4*)(Whi + sso + 16) = *(const uint4*)(hp + 8);                   \
        *(uint4*)(Wlo + sso)      = *(const uint4*)lp;                         \
        *(uint4*)(Wlo + sso + 16) = *(const uint4*)(lp + 8);                   \
    }

// ============================ weight pre-conversion =========================
__global__ void k_cvtW(const float* w0, const float* w1, const float* w2,
                       const float* w3, const float* w4, const float* w5,
                       const float* w6) {
    const float* ws[7] = { w0, w1, w2, w3, w4, w5, w6 };
    int m = blockIdx.y;
    int p = blockIdx.x * blockDim.x + threadIdx.x;
    float2 v = *(const float2*)(ws[m] + p * 2);
    uint32_t hw, lw;
    split2(v, hw, lw);
    *(uint32_t*)&g_Wbf[m][0][p * 2] = hw;
    *(uint32_t*)&g_Wbf[m][1][p * 2] = lw;
}

// ============================ proj GEMM =====================================
__global__ __launch_bounds__(256, 2) void gemm_proj(
    const float* __restrict__ A0f,
    const uint16_t* __restrict__ W0p,
    const float* __restrict__ bias,
    float* __restrict__ Zout,
    int M)
{
    extern __shared__ char smem[];
    float* sbias = (float*)smem;

    uint32_t smemU = (uint32_t)__cvta_generic_to_shared(smem);
    uint32_t AhiB = smemU + 2048;
    uint32_t AloB = AhiB + CPLANE;
    uint32_t WhiB = AloB + CPLANE;
    uint32_t WloB = WhiB + CPLANE;
    char* Ahi = smem + 2048;
    char* Alo = Ahi + CPLANE;
    char* Whi = Alo + CPLANE;
    char* Wlo = Whi + CPLANE;

    int tid = threadIdx.x;
    int wid = tid >> 5;
    int lane = tid & 31;
    int m0 = blockIdx.x * 128;

    if (tid < 128) sbias[tid] = bias[tid];
    __syncthreads();

    int mw = wid & 3, nw = wid >> 2;
    int g = lane >> 2, t = lane & 3;
    int sub = lane >> 3, lr7 = lane & 7;

    int sr = tid & 127;
    int sc0 = (tid >> 7) << 4;
    int sgrow = m0 + sr;
    bool svalid = sgrow < M;
    size_t sso = ((size_t)sr * PADC + sc0) * 2;

    float acc[2][8][4];
    #pragma unroll
    for (int mt = 0; mt < 2; mt++)
        #pragma unroll
        for (int nt = 0; nt < 8; nt++)
            #pragma unroll
            for (int i = 0; i < 4; i++) acc[mt][nt][i] = 0.f;

    for (int kh = 0; kh < 4; kh++) {
        int koff = kh * 32;
        {
            float a[16];
            if (svalid) {
                const float* gp = A0f + (size_t)sgrow * HID + koff + sc0;
                *(float4*)&a[0]  = *(const float4*)(gp);
                *(float4*)&a[4]  = *(const float4*)(gp + 4);
                *(float4*)&a[8]  = *(const float4*)(gp + 8);
                *(float4*)&a[12] = *(const float4*)(gp + 12);
            } else {
                #pragma unroll
                for (int i = 0; i < 16; i++) a[i] = 0.f;
            }
            uint32_t h8[8], l8[8];
            #pragma unroll
            for (int i = 0; i < 8; i++)
                split2(make_float2(a[2 * i], a[2 * i + 1]), h8[i], l8[i]);
            *(uint4*)(Ahi + sso)      = make_uint4(h8[0], h8[1], h8[2], h8[3]);
            *(uint4*)(Ahi + sso + 16) = make_uint4(h8[4], h8[5], h8[6], h8[7]);
            *(uint4*)(Alo + sso)      = make_uint4(l8[0], l8[1], l8[2], l8[3]);
            *(uint4*)(Alo + sso + 16) = make_uint4(l8[4], l8[5], l8[6], l8[7]);
        }
        STAGE_W_CHUNK(W0p)
        __syncthreads();
        GEMM_CHUNK_COMPUTE(AhiB, AloB, WhiB, WloB)
        __syncthreads();
    }

    #pragma unroll
    for (int nt = 0; nt < 8; nt++) {
        int col = nw * 64 + nt * 8 + t * 2;
        float b0v = sbias[col], b1v = sbias[col + 1];
        #pragma unroll
        for (int mt = 0; mt < 2; mt++) {
            int gm = m0 + mw * 32 + mt * 16 + g;
            if (gm < M)
                *(float2*)&Zout[(size_t)gm * HID + col] =
                    make_float2(acc[mt][nt][0] + b0v, acc[mt][nt][1] + b1v);
            if (gm + 8 < M)
                *(float2*)&Zout[(size_t)(gm + 8) * HID + col] =
                    make_float2(acc[mt][nt][2] + b0v, acc[mt][nt][3] + b1v);
        }
    }
}

// ============================ layer GEMM ====================================
// Zout := Abf @ Wl^T + xform(Hin) @ Wr^T + bias ; BN partials.
__global__ __launch_bounds__(256, 2) void gemm_layer(
    const uint16_t* __restrict__ Ahi_g, const uint16_t* __restrict__ Alo_g,
    const float* __restrict__ Hin,
    const float* __restrict__ prevStats,
    const uint16_t* __restrict__ Wlp,
    const uint16_t* __restrict__ Wrp,
    const float* __restrict__ bias,
    float* __restrict__ Zout,
    float* __restrict__ part,
    int M, int hasStats)
{
    extern __shared__ char smem[];
    float* sstats = (float*)smem;
    float* sbias  = (float*)(smem + 1024);
    float* scr    = (float*)(smem + 2048);

    uint32_t smemU = (uint32_t)__cvta_generic_to_shared(smem);
    uint32_t AhiB = smemU + 2048;
    uint32_t AloB = AhiB + CPLANE;
    uint32_t WhiB = AloB + CPLANE;
    uint32_t WloB = WhiB + CPLANE;
    char* Ahi = smem + 2048;
    char* Alo = Ahi + CPLANE;
    char* Whi = Alo + CPLANE;
    char* Wlo = Whi + CPLANE;

    int tid = threadIdx.x;
    int wid = tid >> 5;
    int lane = tid & 31;
    int m0 = blockIdx.x * 128;

    if (tid < 128) sbias[tid] = bias[tid];
    if (hasStats && tid < 256) sstats[tid] = prevStats[tid];
    __syncthreads();

    int mw = wid & 3, nw = wid >> 2;
    int g = lane >> 2, t = lane & 3;
    int sub = lane >> 3, lr7 = lane & 7;

    int sr = tid & 127;
    int sc0 = (tid >> 7) << 4;
    int sgrow = m0 + sr;
    bool svalid = sgrow < M;
    size_t sso = ((size_t)sr * PADC + sc0) * 2;

    float acc[2][8][4];
    #pragma unroll
    for (int mt = 0; mt < 2; mt++)
        #pragma unroll
        for (int nt = 0; nt < 8; nt++)
            #pragma unroll
            for (int i = 0; i < 4; i++) acc[mt][nt][i] = 0.f;

    // ---- pair 0: Abf planes (pure copies) @ Wl^T
    for (int kh = 0; kh < 4; kh++) {
        int koff = kh * 32;
        {
            const uint16_t* hp = Ahi_g + (size_t)sgrow * HID + koff + sc0;
            const uint16_t* lp = Alo_g + (size_t)sgrow * HID + koff + sc0;
            uint4 h0 = svalid ? *(const uint4*)hp       : make_uint4(0, 0, 0, 0);
            uint4 h1 = svalid ? *(const uint4*)(hp + 8) : make_uint4(0, 0, 0, 0);
            uint4 l0 = svalid ? *(const uint4*)lp       : make_uint4(0, 0, 0, 0);
            uint4 l1 = svalid ? *(const uint4*)(lp + 8) : make_uint4(0, 0, 0, 0);
            *(uint4*)(Ahi + sso)      = h0;
            *(uint4*)(Ahi + sso + 16) = h1;
            *(uint4*)(Alo + sso)      = l0;
            *(uint4*)(Alo + sso + 16) = l1;
        }
        STAGE_W_CHUNK(Wlp)
        __syncthreads();
        GEMM_CHUNK_COMPUTE(AhiB, AloB, WhiB, WloB)
        __syncthreads();
    }

    // ---- pair 1: xform(Hin) (convert) @ Wr^T
    for (int kh = 0; kh < 4; kh++) {
        int koff = kh * 32;
        {
            float a[16];
            if (svalid) {
                const float* gp = Hin + (size_t)sgrow * HID + koff + sc0;
                *(float4*)&a[0]  = *(const float4*)(gp);
                *(float4*)&a[4]  = *(const float4*)(gp + 4);
                *(float4*)&a[8]  = *(const float4*)(gp + 8);
                *(float4*)&a[12] = *(const float4*)(gp + 12);
            } else {
                #pragma unroll
                for (int i = 0; i < 16; i++) a[i] = 0.f;
            }
            if (hasStats) {
                int kb = koff + sc0;
                #pragma unroll
                for (int i = 0; i < 16; i++)
                    a[i] = lrelu(fmaf(a[i], sstats[kb + i], sstats[128 + kb + i]));
            }
            uint32_t h8[8], l8[8];
            #pragma unroll
            for (int i = 0; i < 8; i++)
                split2(make_float2(a[2 * i], a[2 * i + 1]), h8[i], l8[i]);
            *(uint4*)(Ahi + sso)      = make_uint4(h8[0], h8[1], h8[2], h8[3]);
            *(uint4*)(Ahi + sso + 16) = make_uint4(h8[4], h8[5], h8[6], h8[7]);
            *(uint4*)(Alo + sso)      = make_uint4(l8[0], l8[1], l8[2], l8[3]);
            *(uint4*)(Alo + sso + 16) = make_uint4(l8[4], l8[5], l8[6], l8[7]);
        }
        STAGE_W_CHUNK(Wrp)
        __syncthreads();
        GEMM_CHUNK_COMPUTE(AhiB, AloB, WhiB, WloB)
        __syncthreads();
    }

    // ---- epilogue: stores + BN partials
    #pragma unroll
    for (int nt = 0; nt < 8; nt++) {
        int col = nw * 64 + nt * 8 + t * 2;
        float b0v = sbias[col], b1v = sbias[col + 1];
        float s0 = 0.f, s1 = 0.f, q0 = 0.f, q1 = 0.f;
        #pragma unroll
        for (int mt = 0; mt < 2; mt++) {
            int gm = m0 + mw * 32 + mt * 16 + g;
            float v00 = acc[mt][nt][0] + b0v;
            float v01 = acc[mt][nt][1] + b1v;
            float v10 = acc[mt][nt][2] + b0v;
            float v11 = acc[mt][nt][3] + b1v;
            if (gm < M) {
                *(float2*)&Zout[(size_t)gm * HID + col] = make_float2(v00, v01);
                s0 += v00; s1 += v01; q0 += v00 * v00; q1 += v01 * v01;
            }
            if (gm + 8 < M) {
                *(float2*)&Zout[(size_t)(gm + 8) * HID + col] = make_float2(v10, v11);
                s0 += v10; s1 += v11; q0 += v10 * v10; q1 += v11 * v11;
            }
        }
        #pragma unroll
        for (int o = 16; o >= 4; o >>= 1) {
            s0 += __shfl_down_sync(0xffffffffu, s0, o);
            s1 += __shfl_down_sync(0xffffffffu, s1, o);
            q0 += __shfl_down_sync(0xffffffffu, q0, o);
            q1 += __shfl_down_sync(0xffffffffu, q1, o);
        }
        if (lane < 4) {
            int c = nw * 64 + nt * 8 + lane * 2;
            scr[mw * 128 + c] = s0;
            scr[mw * 128 + c + 1] = s1;
            scr[512 + mw * 128 + c] = q0;
            scr[512 + mw * 128 + c + 1] = q1;
        }
    }
    __syncthreads();
    if (tid < 128) {
        float s = scr[tid] + scr[128 + tid] + scr[256 + tid] + scr[384 + tid];
        float q = scr[512 + tid] + scr[640 + tid] + scr[768 + tid] + scr[896 + tid];
        part[blockIdx.x * 256 + tid] = s;
        part[blockIdx.x * 256 + 128 + tid] = q;
    }
}

// ============================ CSR construction ==============================
__global__ void k_count(const int* __restrict__ dst, int E) {
    int e = blockIdx.x * blockDim.x + threadIdx.x;
    if (e < E) atomicAdd(&g_deg[dst[e]], 1);
}

__global__ void k_scanA(int M) {
    __shared__ int sh[1024];
    int i = blockIdx.x * 1024 + threadIdx.x;
    int v = (i < M) ? g_deg[i] : 0;
    sh[threadIdx.x] = v;
    __syncthreads();
    #pragma unroll
    for (int d = 1; d < 1024; d <<= 1) {
        int tt = (threadIdx.x >= d) ? sh[threadIdx.x - d] : 0;
        __syncthreads();
        sh[threadIdx.x] += tt;
        __syncthreads();
    }
    if (i < M) g_off[i + 1] = sh[threadIdx.x];
    if (threadIdx.x == 1023) g_bsum[blockIdx.x] = sh[1023];
}

__global__ void k_scanB(int nb) {
    int t = threadIdx.x;
    int orig = (t < nb) ? g_bsum[t] : 0;
    int v = orig;
    #pragma unroll
    for (int o = 1; o < 32; o <<= 1) {
        int u = __shfl_up_sync(0xffffffffu, v, o);
        if ((t & 31) >= o) v += u;
    }
    __shared__ int ws[4];
    if ((t & 31) == 31) ws[t >> 5] = v;
    __syncthreads();
    int add = 0;
    #pragma unroll
    for (int w = 0; w < 4; w++) add += (w < (t >> 5)) ? ws[w] : 0;
    v += add;
    if (t < nb) g_bsum[t] = v - orig;
}

__global__ void k_scanC(int M) {
    int i = blockIdx.x * blockDim.x + threadIdx.x;
    if (i < M) {
        int inc = g_off[i + 1] + g_bsum[i >> 10];
        g_off[i + 1] = inc;
        g_cur[i] = inc - g_deg[i];
        if (i == 0) g_off[0] = 0;
    }
}

__global__ void k_scatter(const int* __restrict__ src, const int* __restrict__ dst, int E) {
    int e = blockIdx.x * blockDim.x + threadIdx.x;
    if (e < E) {
        int pos = atomicAdd(&g_cur[dst[e]], 1);
        g_srcs[pos] = src[e];
    }
}

// ============================ max aggregation ===============================
__global__ __launch_bounds__(256) void k_agg(const float* __restrict__ Hin,
                                             const float* __restrict__ stats,
                                             int hasStats, int M)
{
    int n = blockIdx.x * 8 + (threadIdx.x >> 5);
    if (n >= M) return;
    int lane = threadIdx.x & 31;

    float4 sc, sh;
    if (hasStats) {
        sc = *(const float4*)&stats[lane * 4];
        sh = *(const float4*)&stats[128 + lane * 4];
    }

    int s = g_off[n], e = g_off[n + 1];
    float4 m = make_float4(-3.4e38f, -3.4e38f, -3.4e38f, -3.4e38f);
    int j = s;
    for (; j + 4 <= e; j += 4) {
        int s0 = g_srcs[j], s1 = g_srcs[j + 1], s2 = g_srcs[j + 2], s3 = g_srcs[j + 3];
        float4 v0 = *(const float4*)&Hin[(size_t)s0 * HID + lane * 4];
        float4 v1 = *(const float4*)&Hin[(size_t)s1 * HID + lane * 4];
        float4 v2 = *(const float4*)&Hin[(size_t)s2 * HID + lane * 4];
        float4 v3 = *(const float4*)&Hin[(size_t)s3 * HID + lane * 4];
        if (hasStats) {
            v0 = xform4(v0, sc, sh); v1 = xform4(v1, sc, sh);
            v2 = xform4(v2, sc, sh); v3 = xform4(v3, sc, sh);
        }
        m = max4(m, max4(max4(v0, v1), max4(v2, v3)));
    }
    for (; j < e; ++j) {
        float4 v = *(const float4*)&Hin[(size_t)g_srcs[j] * HID + lane * 4];
        if (hasStats) v = xform4(v, sc, sh);
        m = max4(m, v);
    }
    if (e == s) m = make_float4(0.f, 0.f, 0.f, 0.f);

    uint32_t h0, l0, h1, l1;
    split2(make_float2(m.x, m.y), h0, l0);
    split2(make_float2(m.z, m.w), h1, l1);
    size_t off = (size_t)n * HID + lane * 4;
    *(uint2*)&g_AbfHi[off] = make_uint2(h0, h1);
    *(uint2*)&g_AbfLo[off] = make_uint2(l0, l1);
}

// ============================ BN stats finalize =============================
__global__ __launch_bounds__(1024) void k_bnfinal(
    const float* __restrict__ g, const float* __restrict__ be,
    float* __restrict__ statsOut, int M, int NB)
{
    __shared__ double sD[8][128];
    __shared__ double qD[8][128];
    int tid = threadIdx.x;
    int grp = tid >> 7;
    int c = tid & 127;
    double s = 0.0, q = 0.0;
    for (int b = grp; b < NB; b += 8) {
        s += (double)g_part[b * 256 + c];
        q += (double)g_part[b * 256 + 128 + c];
    }
    sD[grp][c] = s; qD[grp][c] = q;
    __syncthreads();
    if (tid < 128) {
        double ss = 0.0, qq = 0.0;
        #pragma unroll
        for (int gg = 0; gg < 8; gg++) { ss += sD[gg][tid]; qq += qD[gg][tid]; }
        double mean = ss / (double)M;
        double var = qq / (double)M - mean * mean;
        float rstd = (float)(1.0 / sqrt(var + 1e-5));
        float scale = g[tid] * rstd;
        statsOut[tid] = scale;
        statsOut[128 + tid] = be[tid] - (float)mean * scale;
    }
}

// ============================ head (warp per row) ===========================
__global__ __launch_bounds__(256) void k_fc(
    const float* __restrict__ Zlast, const float* __restrict__ stats,
    const float* __restrict__ W1, const float* __restrict__ b1,
    const float* __restrict__ W2, const float* __restrict__ b2,
    float* __restrict__ out, int M)
{
    __shared__ float W1s[64][132];
    __shared__ float b1s[64], w2s[64];
    __shared__ float xsh[8][128];

    int tid = threadIdx.x;
    int wid = tid >> 5;
    int lane = tid & 31;

    for (int i = tid; i < 64 * 128; i += 256) W1s[i >> 7][i & 127] = W1[i];
    if (tid < 64) { b1s[tid] = b1[tid]; w2s[tid] = W2[tid]; }
    __syncthreads();

    float4 sc = *(const float4*)&stats[lane * 4];
    float4 sh = *(const float4*)&stats[128 + lane * 4];
    float bias2 = b2[0];
    float w2a = w2s[lane], w2b = w2s[lane + 32];
    float b1a = b1s[lane], b1b = b1s[lane + 32];

    const int ROWS = 8;
    int rbase = blockIdx.x * (8 * ROWS) + wid * ROWS;

    for (int rr = 0; rr < ROWS; rr++) {
        int r = rbase + rr;
        if (r >= M) return;
        float4 z = *(const float4*)&Zlast[(size_t)r * HID + lane * 4];
        float4 h = *(const float4*)&g_H0[(size_t)r * HID + lane * 4];
        z = xform4(z, sc, sh);
        z.x += h.x; z.y += h.y; z.z += h.z; z.w += h.w;
        *(float4*)&xsh[wid][lane * 4] = z;
        __syncwarp();

        float acc0 = 0.f, acc1 = 0.f;
        #pragma unroll
        for (int k = 0; k < 128; k += 4) {
            float4 xv = *(const float4*)&xsh[wid][k];
            float4 w0 = *(const float4*)&W1s[lane][k];
            float4 w1 = *(const float4*)&W1s[lane + 32][k];
            acc0 = fmaf(xv.x, w0.x, acc0); acc0 = fmaf(xv.y, w0.y, acc0);
            acc0 = fmaf(xv.z, w0.z, acc0); acc0 = fmaf(xv.w, w0.w, acc0);
            acc1 = fmaf(xv.x, w1.x, acc1); acc1 = fmaf(xv.y, w1.y, acc1);
            acc1 = fmaf(xv.z, w1.z, acc1); acc1 = fmaf(xv.w, w1.w, acc1);
        }
        float f0 = lrelu(acc0 + b1a);
        float f1 = lrelu(acc1 + b1b);
        float contrib = f0 * w2a + f1 * w2b;
        #pragma unroll
        for (int o = 16; o > 0; o >>= 1)
            contrib += __shfl_down_sync(0xffffffffu, contrib, o);
        if (lane == 0) out[r] = contrib + bias2;
        __syncwarp();
    }
}

// ============================ launch ========================================
extern "C" void kernel_launch(void* const* d_in, const int* in_sizes, int n_in,
                              void* d_out, int out_size)
{
    const float* x    = (const float*)d_in[0];
    const int*   ei   = (const int*)d_in[1];
    const float* W_in = (const float*)d_in[2];
    const float* b_in = (const float*)d_in[3];
    const float* Wl[3] = { (const float*)d_in[4], (const float*)d_in[7], (const float*)d_in[10] };
    const float* bl[3] = { (const float*)d_in[5], (const float*)d_in[8], (const float*)d_in[11] };
    const float* Wr[3] = { (const float*)d_in[6], (const float*)d_in[9], (const float*)d_in[12] };
    const float* gm[3] = { (const float*)d_in[13], (const float*)d_in[15], (const float*)d_in[17] };
    const float* be[3] = { (const float*)d_in[14], (const float*)d_in[16], (const float*)d_in[18] };
    const float* W_fc1 = (const float*)d_in[19];
    const float* b_fc1 = (const float*)d_in[20];
    const float* W_fc2 = (const float*)d_in[21];
    const float* b_fc2 = (const float*)d_in[22];
    float* out = (float*)d_out;

    int M = in_sizes[0] / HID;
    int E = in_sizes[1] / 2;
    const int* src = ei;
    const int* dst = ei + E;

    cudaFuncSetAttribute(gemm_proj, cudaFuncAttributeMaxDynamicSharedMemorySize,
                         SM_GEMM_TOTAL);
    cudaFuncSetAttribute(gemm_layer, cudaFuncAttributeMaxDynamicSharedMemorySize,
                         SM_GEMM_TOTAL);

    void *pH0v, *pZv, *pPartv, *pStatsv, *pDegv, *pAHv, *pALv, *pWv;
    cudaGetSymbolAddress(&pH0v, g_H0);
    cudaGetSymbolAddress(&pZv, g_Zb);
    cudaGetSymbolAddress(&pPartv, g_part);
    cudaGetSymbolAddress(&pStatsv, g_statsBuf);
    cudaGetSymbolAddress(&pDegv, g_deg);
    cudaGetSymbolAddress(&pAHv, g_AbfHi);
    cudaGetSymbolAddress(&pALv, g_AbfLo);
    cudaGetSymbolAddress(&pWv, g_Wbf);
    float* pH0 = (float*)pH0v;
    float* pZ0 = (float*)pZv;
    float* pZ1 = pZ0 + (size_t)NMAX * HID;
    float* pPart = (float*)pPartv;
    float* pStats0 = (float*)pStatsv;
    float* pStats1 = pStats0 + 256;
    uint16_t* pAH = (uint16_t*)pAHv;
    uint16_t* pAL = (uint16_t*)pALv;
    uint16_t* pW  = (uint16_t*)pWv;
    uint16_t* pWm[7];
    for (int i = 0; i < 7; i++) pWm[i] = pW + (size_t)i * 2 * 16384;

    int scanBlocks = (M + 1023) / 1024;
    int gemmGrid = (M + 127) / 128;
    int aggGrid = (M + 7) / 8;

    // ---- setup + CSR build; proj GEMM is the 4th launch (ncu target)
    cudaMemsetAsync(pDegv, 0, (size_t)M * sizeof(int));
    k_cvtW<<<dim3(32, 7), 256>>>(W_in, Wl[0], Wr[0], Wl[1], Wr[1], Wl[2], Wr[2]); // 1
    k_count<<<(E + 511) / 512, 512>>>(dst, E);                                     // 2
    k_scanA<<<scanBlocks, 1024>>>(M);                                              // 3
    gemm_proj<<<gemmGrid, 256, SM_GEMM_TOTAL>>>(x, pWm[0], b_in, pH0, M);          // 4 (profiled)
    k_scanB<<<1, 128>>>(scanBlocks);
    k_scanC<<<(M + 255) / 256, 256>>>(M);
    k_scatter<<<(E + 511) / 512, 512>>>(src, dst, E);

    // ---- layer 1 (agg over H0, no xform)
    k_agg<<<aggGrid, 256>>>(pH0, nullptr, 0, M);
    gemm_layer<<<gemmGrid, 256, SM_GEMM_TOTAL>>>(pAH, pAL, pH0, nullptr,
                                                 pWm[1], pWm[2], bl[0],
                                                 pZ0, pPart, M, 0);
    k_bnfinal<<<1, 1024>>>(gm[0], be[0], pStats0, M, gemmGrid);

    // ---- layer 2
    k_agg<<<aggGrid, 256>>>(pZ0, pStats0, 1, M);
    gemm_layer<<<gemmGrid, 256, SM_GEMM_TOTAL>>>(pAH, pAL, pZ0, pStats0,
                                                 pWm[3], pWm[4], bl[1],
                                                 pZ1, pPart, M, 1);
    k_bnfinal<<<1, 1024>>>(gm[1], be[1], pStats1, M, gemmGrid);

    // ---- layer 3
    k_agg<<<aggGrid, 256>>>(pZ1, pStats1, 1, M);
    gemm_layer<<<gemmGrid, 256, SM_GEMM_TOTAL>>>(pAH, pAL, pZ1, pStats1,
                                                 pWm[5], pWm[6], bl[2],
                                                 pZ0, pPart, M, 1);
    k_bnfinal<<<1, 1024>>>(gm[2], be[2], pStats0, M, gemmGrid);

    // ---- head
    k_fc<<<(M + 63) / 64, 256>>>(pZ0, pStats0, W_fc1, b_fc1, W_fc2, b_fc2, out, M);
}

// round 16
// speedup vs baseline: 1.3522x; 1.0015x over previous
#include <cuda_runtime.h>
#include <cuda_bf16.h>
#include <stdint.h>

// GraphSAGE max-agg pipeline. R16 = R15 + k_agg ILP: 8x unrolled neighbor
// loop (8 LDG.128 in flight per lane) + coalesced index fetch via shfl.

#define NMAX 100000
#define EMAX 1600000
#define HID 128
#define NEG 0.01f
#define GBMAX 800

#define PADC 40
#define CPLANE (128 * PADC * 2)
#define SM_GEMM_TOTAL (2048 + 4 * CPLANE)   // 43008 B -> 2 CTAs/SM

#define LDSM_X4(r0, r1, r2, r3, addr) \
    asm volatile("ldmatrix.sync.aligned.m8n8.x4.shared.b16 {%0,%1,%2,%3}, [%4];" \
                 : "=r"(r0), "=r"(r1), "=r"(r2), "=r"(r3) : "r"(addr))

// -------------------- device scratch ---------------------------------------
__device__ float    g_H0[NMAX * HID];
__device__ float    g_Zb[2][NMAX * HID];
__device__ uint16_t g_AbfHi[NMAX * HID];
__device__ uint16_t g_AbfLo[NMAX * HID];
__device__ uint16_t g_Wbf[7][2][128 * 128];
__device__ int   g_deg [NMAX];
__device__ int   g_off [NMAX + 1];
__device__ int   g_cur [NMAX];
__device__ int   g_srcs[EMAX];
__device__ float g_part[GBMAX * 256];
__device__ float g_statsBuf[2][256];
__device__ int   g_bsum[128];

// -------------------- helpers ----------------------------------------------
__device__ __forceinline__ float lrelu(float x) { return fmaxf(x, NEG * x); }

__device__ __forceinline__ float4 xform4(float4 v, float4 sc, float4 sh) {
    v.x = lrelu(fmaf(v.x, sc.x, sh.x));
    v.y = lrelu(fmaf(v.y, sc.y, sh.y));
    v.z = lrelu(fmaf(v.z, sc.z, sh.z));
    v.w = lrelu(fmaf(v.w, sc.w, sh.w));
    return v;
}
__device__ __forceinline__ float4 max4(float4 a, float4 b) {
    a.x = fmaxf(a.x, b.x); a.y = fmaxf(a.y, b.y);
    a.z = fmaxf(a.z, b.z); a.w = fmaxf(a.w, b.w);
    return a;
}

__device__ __forceinline__ void mma16816(float* c, const uint32_t* a,
                                         uint32_t b0, uint32_t b1) {
    asm volatile(
        "mma.sync.aligned.m16n8k16.row.col.f32.bf16.bf16.f32 "
        "{%0,%1,%2,%3}, {%4,%5,%6,%7}, {%8,%9}, {%0,%1,%2,%3};"
        : "+f"(c[0]), "+f"(c[1]), "+f"(c[2]), "+f"(c[3])
        : "r"(a[0]), "r"(a[1]), "r"(a[2]), "r"(a[3]), "r"(b0), "r"(b1));
}

__device__ __forceinline__ void split2(float2 v, uint32_t& h, uint32_t& l) {
    __nv_bfloat16 h0 = __float2bfloat16(v.x);
    __nv_bfloat16 h1 = __float2bfloat16(v.y);
    float l0 = v.x - __bfloat162float(h0);
    float l1 = v.y - __bfloat162float(h1);
    __nv_bfloat162 hp; hp.x = h0; hp.y = h1;
    __nv_bfloat162 lp; lp.x = __float2bfloat16(l0); lp.y = __float2bfloat16(l1);
    h = *(uint32_t*)&hp;
    l = *(uint32_t*)&lp;
}

#define GEMM_CHUNK_COMPUTE(AhiB, AloB, WhiB, WloB)                             \
    _Pragma("unroll")                                                          \
    for (int ks = 0; ks < 2; ks++) {                                           \
        int k0 = ks * 16;                                                      \
        uint32_t ah[2][4], al[2][4];                                           \
        _Pragma("unroll")                                                      \
        for (int mt = 0; mt < 2; mt++) {                                       \
            uint32_t off = (uint32_t)(((mw * 32 + mt * 16 + (sub & 1) * 8 + lr7) * PADC) \
                                      + k0 + (sub >> 1) * 8) * 2;              \
            LDSM_X4(ah[mt][0], ah[mt][1], ah[mt][2], ah[mt][3], (AhiB) + off); \
            LDSM_X4(al[mt][0], al[mt][1], al[mt][2], al[mt][3], (AloB) + off); \
        }                                                                      \
        uint32_t bh[8][2], bl[8][2];                                           \
        _Pragma("unroll")                                                      \
        for (int p = 0; p < 4; p++) {                                          \
            uint32_t off = (uint32_t)(((nw * 64 + p * 16 + (sub >> 1) * 8 + lr7) * PADC) \
                                      + k0 + (sub & 1) * 8) * 2;               \
            LDSM_X4(bh[2 * p][0], bh[2 * p][1], bh[2 * p + 1][0], bh[2 * p + 1][1], \
                    (WhiB) + off);                                             \
            LDSM_X4(bl[2 * p][0], bl[2 * p][1], bl[2 * p + 1][0], bl[2 * p + 1][1], \
                    (WloB) + off);                                             \
        }                                                                      \
        _Pragma("unroll")                                                      \
        for (int nt = 0; nt < 8; nt++)                                         \
            _Pragma("unroll")                                                  \
            for (int mt = 0; mt < 2; mt++) {                                   \
                mma16816(acc[mt][nt], ah[mt], bh[nt][0], bh[nt][1]);           \
                mma16816(acc[mt][nt], al[mt], bh[nt][0], bh[nt][1]);           \
                mma16816(acc[mt][nt], ah[mt], bl[nt][0], bl[nt][1]);           \
            }                                                                  \
    }

#define STAGE_W_CHUNK(Wp)                                                      \
    {                                                                          \
        const uint16_t* hp = (Wp) + (size_t)sr * HID + koff + sc0;             \
        const uint16_t* lp = hp + 16384;                                       \
        *(uint4*)(Whi + sso)      = *(const uint4*)hp;                         \
        *(uint4*)(Whi + sso + 16) = *(const uint4*)(hp + 8);                   \
        *(uint4*)(Wlo + sso)      = *(const uint4*)lp;                         \
        *(uint4*)(Wlo + sso + 16) = *(const uint4*)(lp + 8);                   \
    }

// ============================ weight pre-conversion =========================
__global__ void k_cvtW(const float* w0, const float* w1, const float* w2,
                       const float* w3, const float* w4, const float* w5,
                       const float* w6) {
    const float* ws[7] = { w0, w1, w2, w3, w4, w5, w6 };
    int m = blockIdx.y;
    int p = blockIdx.x * blockDim.x + threadIdx.x;
    float2 v = *(const float2*)(ws[m] + p * 2);
    uint32_t hw, lw;
    split2(v, hw, lw);
    *(uint32_t*)&g_Wbf[m][0][p * 2] = hw;
    *(uint32_t*)&g_Wbf[m][1][p * 2] = lw;
}

// ============================ proj GEMM =====================================
__global__ __launch_bounds__(256, 2) void gemm_proj(
    const float* __restrict__ A0f,
    const uint16_t* __restrict__ W0p,
    const float* __restrict__ bias,
    float* __restrict__ Zout,
    int M)
{
    extern __shared__ char smem[];
    float* sbias = (float*)smem;

    uint32_t smemU = (uint32_t)__cvta_generic_to_shared(smem);
    uint32_t AhiB = smemU + 2048;
    uint32_t AloB = AhiB + CPLANE;
    uint32_t WhiB = AloB + CPLANE;
    uint32_t WloB = WhiB + CPLANE;
    char* Ahi = smem + 2048;
    char* Alo = Ahi + CPLANE;
    char* Whi = Alo + CPLANE;
    char* Wlo = Whi + CPLANE;

    int tid = threadIdx.x;
    int wid = tid >> 5;
    int lane = tid & 31;
    int m0 = blockIdx.x * 128;

    if (tid < 128) sbias[tid] = bias[tid];
    __syncthreads();

    int mw = wid & 3, nw = wid >> 2;
    int g = lane >> 2, t = lane & 3;
    int sub = lane >> 3, lr7 = lane & 7;

    int sr = tid & 127;
    int sc0 = (tid >> 7) << 4;
    int sgrow = m0 + sr;
    bool svalid = sgrow < M;
    size_t sso = ((size_t)sr * PADC + sc0) * 2;

    float acc[2][8][4];
    #pragma unroll
    for (int mt = 0; mt < 2; mt++)
        #pragma unroll
        for (int nt = 0; nt < 8; nt++)
            #pragma unroll
            for (int i = 0; i < 4; i++) acc[mt][nt][i] = 0.f;

    for (int kh = 0; kh < 4; kh++) {
        int koff = kh * 32;
        {
            float a[16];
            if (svalid) {
                const float* gp = A0f + (size_t)sgrow * HID + koff + sc0;
                *(float4*)&a[0]  = *(const float4*)(gp);
                *(float4*)&a[4]  = *(const float4*)(gp + 4);
                *(float4*)&a[8]  = *(const float4*)(gp + 8);
                *(float4*)&a[12] = *(const float4*)(gp + 12);
            } else {
                #pragma unroll
                for (int i = 0; i < 16; i++) a[i] = 0.f;
            }
            uint32_t h8[8], l8[8];
            #pragma unroll
            for (int i = 0; i < 8; i++)
                split2(make_float2(a[2 * i], a[2 * i + 1]), h8[i], l8[i]);
            *(uint4*)(Ahi + sso)      = make_uint4(h8[0], h8[1], h8[2], h8[3]);
            *(uint4*)(Ahi + sso + 16) = make_uint4(h8[4], h8[5], h8[6], h8[7]);
            *(uint4*)(Alo + sso)      = make_uint4(l8[0], l8[1], l8[2], l8[3]);
            *(uint4*)(Alo + sso + 16) = make_uint4(l8[4], l8[5], l8[6], l8[7]);
        }
        STAGE_W_CHUNK(W0p)
        __syncthreads();
        GEMM_CHUNK_COMPUTE(AhiB, AloB, WhiB, WloB)
        __syncthreads();
    }

    #pragma unroll
    for (int nt = 0; nt < 8; nt++) {
        int col = nw * 64 + nt * 8 + t * 2;
        float b0v = sbias[col], b1v = sbias[col + 1];
        #pragma unroll
        for (int mt = 0; mt < 2; mt++) {
            int gm = m0 + mw * 32 + mt * 16 + g;
            if (gm < M)
                *(float2*)&Zout[(size_t)gm * HID + col] =
                    make_float2(acc[mt][nt][0] + b0v, acc[mt][nt][1] + b1v);
            if (gm + 8 < M)
                *(float2*)&Zout[(size_t)(gm + 8) * HID + col] =
                    make_float2(acc[mt][nt][2] + b0v, acc[mt][nt][3] + b1v);
        }
    }
}

// ============================ layer GEMM ====================================
__global__ __launch_bounds__(256, 2) void gemm_layer(
    const uint16_t* __restrict__ Ahi_g, const uint16_t* __restrict__ Alo_g,
    const float* __restrict__ Hin,
    const float* __restrict__ prevStats,
    const uint16_t* __restrict__ Wlp,
    const uint16_t* __restrict__ Wrp,
    const float* __restrict__ bias,
    float* __restrict__ Zout,
    float* __restrict__ part,
    int M, int hasStats)
{
    extern __shared__ char smem[];
    float* sstats = (float*)smem;
    float* sbias  = (float*)(smem + 1024);
    float* scr    = (float*)(smem + 2048);

    uint32_t smemU = (uint32_t)__cvta_generic_to_shared(smem);
    uint32_t AhiB = smemU + 2048;
    uint32_t AloB = AhiB + CPLANE;
    uint32_t WhiB = AloB + CPLANE;
    uint32_t WloB = WhiB + CPLANE;
    char* Ahi = smem + 2048;
    char* Alo = Ahi + CPLANE;
    char* Whi = Alo + CPLANE;
    char* Wlo = Whi + CPLANE;

    int tid = threadIdx.x;
    int wid = tid >> 5;
    int lane = tid & 31;
    int m0 = blockIdx.x * 128;

    if (tid < 128) sbias[tid] = bias[tid];
    if (hasStats && tid < 256) sstats[tid] = prevStats[tid];
    __syncthreads();

    int mw = wid & 3, nw = wid >> 2;
    int g = lane >> 2, t = lane & 3;
    int sub = lane >> 3, lr7 = lane & 7;

    int sr = tid & 127;
    int sc0 = (tid >> 7) << 4;
    int sgrow = m0 + sr;
    bool svalid = sgrow < M;
    size_t sso = ((size_t)sr * PADC + sc0) * 2;

    float acc[2][8][4];
    #pragma unroll
    for (int mt = 0; mt < 2; mt++)
        #pragma unroll
        for (int nt = 0; nt < 8; nt++)
            #pragma unroll
            for (int i = 0; i < 4; i++) acc[mt][nt][i] = 0.f;

    // ---- pair 0: Abf planes (pure copies) @ Wl^T
    for (int kh = 0; kh < 4; kh++) {
        int koff = kh * 32;
        {
            const uint16_t* hp = Ahi_g + (size_t)sgrow * HID + koff + sc0;
            const uint16_t* lp = Alo_g + (size_t)sgrow * HID + koff + sc0;
            uint4 h0 = svalid ? *(const uint4*)hp       : make_uint4(0, 0, 0, 0);
            uint4 h1 = svalid ? *(const uint4*)(hp + 8) : make_uint4(0, 0, 0, 0);
            uint4 l0 = svalid ? *(const uint4*)lp       : make_uint4(0, 0, 0, 0);
            uint4 l1 = svalid ? *(const uint4*)(lp + 8) : make_uint4(0, 0, 0, 0);
            *(uint4*)(Ahi + sso)      = h0;
            *(uint4*)(Ahi + sso + 16) = h1;
            *(uint4*)(Alo + sso)      = l0;
            *(uint4*)(Alo + sso + 16) = l1;
        }
        STAGE_W_CHUNK(Wlp)
        __syncthreads();
        GEMM_CHUNK_COMPUTE(AhiB, AloB, WhiB, WloB)
        __syncthreads();
    }

    // ---- pair 1: xform(Hin) (convert) @ Wr^T
    for (int kh = 0; kh < 4; kh++) {
        int koff = kh * 32;
        {
            float a[16];
            if (svalid) {
                const float* gp = Hin + (size_t)sgrow * HID + koff + sc0;
                *(float4*)&a[0]  = *(const float4*)(gp);
                *(float4*)&a[4]  = *(const float4*)(gp + 4);
                *(float4*)&a[8]  = *(const float4*)(gp + 8);
                *(float4*)&a[12] = *(const float4*)(gp + 12);
            } else {
                #pragma unroll
                for (int i = 0; i < 16; i++) a[i] = 0.f;
            }
            if (hasStats) {
                int kb = koff + sc0;
                #pragma unroll
                for (int i = 0; i < 16; i++)
                    a[i] = lrelu(fmaf(a[i], sstats[kb + i], sstats[128 + kb + i]));
            }
            uint32_t h8[8], l8[8];
            #pragma unroll
            for (int i = 0; i < 8; i++)
                split2(make_float2(a[2 * i], a[2 * i + 1]), h8[i], l8[i]);
            *(uint4*)(Ahi + sso)      = make_uint4(h8[0], h8[1], h8[2], h8[3]);
            *(uint4*)(Ahi + sso + 16) = make_uint4(h8[4], h8[5], h8[6], h8[7]);
            *(uint4*)(Alo + sso)      = make_uint4(l8[0], l8[1], l8[2], l8[3]);
            *(uint4*)(Alo + sso + 16) = make_uint4(l8[4], l8[5], l8[6], l8[7]);
        }
        STAGE_W_CHUNK(Wrp)
        __syncthreads();
        GEMM_CHUNK_COMPUTE(AhiB, AloB, WhiB, WloB)
        __syncthreads();
    }

    // ---- epilogue: stores + BN partials
    #pragma unroll
    for (int nt = 0; nt < 8; nt++) {
        int col = nw * 64 + nt * 8 + t * 2;
        float b0v = sbias[col], b1v = sbias[col + 1];
        float s0 = 0.f, s1 = 0.f, q0 = 0.f, q1 = 0.f;
        #pragma unroll
        for (int mt = 0; mt < 2; mt++) {
            int gm = m0 + mw * 32 + mt * 16 + g;
            float v00 = acc[mt][nt][0] + b0v;
            float v01 = acc[mt][nt][1] + b1v;
            float v10 = acc[mt][nt][2] + b0v;
            float v11 = acc[mt][nt][3] + b1v;
            if (gm < M) {
                *(float2*)&Zout[(size_t)gm * HID + col] = make_float2(v00, v01);
                s0 += v00; s1 += v01; q0 += v00 * v00; q1 += v01 * v01;
            }
            if (gm + 8 < M) {
                *(float2*)&Zout[(size_t)(gm + 8) * HID + col] = make_float2(v10, v11);
                s0 += v10; s1 += v11; q0 += v10 * v10; q1 += v11 * v11;
            }
        }
        #pragma unroll
        for (int o = 16; o >= 4; o >>= 1) {
            s0 += __shfl_down_sync(0xffffffffu, s0, o);
            s1 += __shfl_down_sync(0xffffffffu, s1, o);
            q0 += __shfl_down_sync(0xffffffffu, q0, o);
            q1 += __shfl_down_sync(0xffffffffu, q1, o);
        }
        if (lane < 4) {
            int c = nw * 64 + nt * 8 + lane * 2;
            scr[mw * 128 + c] = s0;
            scr[mw * 128 + c + 1] = s1;
            scr[512 + mw * 128 + c] = q0;
            scr[512 + mw * 128 + c + 1] = q1;
        }
    }
    __syncthreads();
    if (tid < 128) {
        float s = scr[tid] + scr[128 + tid] + scr[256 + tid] + scr[384 + tid];
        float q = scr[512 + tid] + scr[640 + tid] + scr[768 + tid] + scr[896 + tid];
        part[blockIdx.x * 256 + tid] = s;
        part[blockIdx.x * 256 + 128 + tid] = q;
    }
}

// ============================ CSR construction ==============================
__global__ void k_count(const int* __restrict__ dst, int E) {
    int e = blockIdx.x * blockDim.x + threadIdx.x;
    if (e < E) atomicAdd(&g_deg[dst[e]], 1);
}

__global__ void k_scanA(int M) {
    __shared__ int sh[1024];
    int i = blockIdx.x * 1024 + threadIdx.x;
    int v = (i < M) ? g_deg[i] : 0;
    sh[threadIdx.x] = v;
    __syncthreads();
    #pragma unroll
    for (int d = 1; d < 1024; d <<= 1) {
        int tt = (threadIdx.x >= d) ? sh[threadIdx.x - d] : 0;
        __syncthreads();
        sh[threadIdx.x] += tt;
        __syncthreads();
    }
    if (i < M) g_off[i + 1] = sh[threadIdx.x];
    if (threadIdx.x == 1023) g_bsum[blockIdx.x] = sh[1023];
}

__global__ void k_scanB(int nb) {
    int t = threadIdx.x;
    int orig = (t < nb) ? g_bsum[t] : 0;
    int v = orig;
    #pragma unroll
    for (int o = 1; o < 32; o <<= 1) {
        int u = __shfl_up_sync(0xffffffffu, v, o);
        if ((t & 31) >= o) v += u;
    }
    __shared__ int ws[4];
    if ((t & 31) == 31) ws[t >> 5] = v;
    __syncthreads();
    int add = 0;
    #pragma unroll
    for (int w = 0; w < 4; w++) add += (w < (t >> 5)) ? ws[w] : 0;
    v += add;
    if (t < nb) g_bsum[t] = v - orig;
}

__global__ void k_scanC(int M) {
    int i = blockIdx.x * blockDim.x + threadIdx.x;
    if (i < M) {
        int inc = g_off[i + 1] + g_bsum[i >> 10];
        g_off[i + 1] = inc;
        g_cur[i] = inc - g_deg[i];
        if (i == 0) g_off[0] = 0;
    }
}

__global__ void k_scatter(const int* __restrict__ src, const int* __restrict__ dst, int E) {
    int e = blockIdx.x * blockDim.x + threadIdx.x;
    if (e < E) {
        int pos = atomicAdd(&g_cur[dst[e]], 1);
        g_srcs[pos] = src[e];
    }
}

// ============================ max aggregation ===============================
// warp per node; 8x unrolled gather with coalesced index fetch via shfl.
__global__ __launch_bounds__(256) void k_agg(const float* __restrict__ Hin,
                                             const float* __restrict__ stats,
                                             int hasStats, int M)
{
    int n = blockIdx.x * 8 + (threadIdx.x >> 5);
    if (n >= M) return;
    int lane = threadIdx.x & 31;

    float4 sc, sh;
    if (hasStats) {
        sc = *(const float4*)&stats[lane * 4];
        sh = *(const float4*)&stats[128 + lane * 4];
    }

    int s = g_off[n], e = g_off[n + 1];
    float4 m = make_float4(-3.4e38f, -3.4e38f, -3.4e38f, -3.4e38f);
    int j = s;
    for (; j + 8 <= e; j += 8) {
        int idx = (lane < 8) ? g_srcs[j + lane] : 0;   // coalesced fetch
        int si[8];
        #pragma unroll
        for (int i = 0; i < 8; i++) si[i] = __shfl_sync(0xffffffffu, idx, i);
        float4 v[8];
        #pragma unroll
        for (int i = 0; i < 8; i++)
            v[i] = *(const float4*)&Hin[(size_t)si[i] * HID + lane * 4];
        if (hasStats) {
            #pragma unroll
            for (int i = 0; i < 8; i++) v[i] = xform4(v[i], sc, sh);
        }
        float4 m01 = max4(v[0], v[1]);
        float4 m23 = max4(v[2], v[3]);
        float4 m45 = max4(v[4], v[5]);
        float4 m67 = max4(v[6], v[7]);
        m = max4(m, max4(max4(m01, m23), max4(m45, m67)));
    }
    for (; j < e; ++j) {
        float4 v = *(const float4*)&Hin[(size_t)g_srcs[j] * HID + lane * 4];
        if (hasStats) v = xform4(v, sc, sh);
        m = max4(m, v);
    }
    if (e == s) m = make_float4(0.f, 0.f, 0.f, 0.f);

    uint32_t h0, l0, h1, l1;
    split2(make_float2(m.x, m.y), h0, l0);
    split2(make_float2(m.z, m.w), h1, l1);
    size_t off = (size_t)n * HID + lane * 4;
    *(uint2*)&g_AbfHi[off] = make_uint2(h0, h1);
    *(uint2*)&g_AbfLo[off] = make_uint2(l0, l1);
}

// ============================ BN stats finalize =============================
__global__ __launch_bounds__(1024) void k_bnfinal(
    const float* __restrict__ g, const float* __restrict__ be,
    float* __restrict__ statsOut, int M, int NB)
{
    __shared__ double sD[8][128];
    __shared__ double qD[8][128];
    int tid = threadIdx.x;
    int grp = tid >> 7;
    int c = tid & 127;
    double s = 0.0, q = 0.0;
    for (int b = grp; b < NB; b += 8) {
        s += (double)g_part[b * 256 + c];
        q += (double)g_part[b * 256 + 128 + c];
    }
    sD[grp][c] = s; qD[grp][c] = q;
    __syncthreads();
    if (tid < 128) {
        double ss = 0.0, qq = 0.0;
        #pragma unroll
        for (int gg = 0; gg < 8; gg++) { ss += sD[gg][tid]; qq += qD[gg][tid]; }
        double mean = ss / (double)M;
        double var = qq / (double)M - mean * mean;
        float rstd = (float)(1.0 / sqrt(var + 1e-5));
        float scale = g[tid] * rstd;
        statsOut[tid] = scale;
        statsOut[128 + tid] = be[tid] - (float)mean * scale;
    }
}

// ============================ head (warp per row) ===========================
__global__ __launch_bounds__(256) void k_fc(
    const float* __restrict__ Zlast, const float* __restrict__ stats,
    const float* __restrict__ W1, const float* __restrict__ b1,
    const float* __restrict__ W2, const float* __restrict__ b2,
    float* __restrict__ out, int M)
{
    __shared__ float W1s[64][132];
    __shared__ float b1s[64], w2s[64];
    __shared__ float xsh[8][128];

    int tid = threadIdx.x;
    int wid = tid >> 5;
    int lane = tid & 31;

    for (int i = tid; i < 64 * 128; i += 256) W1s[i >> 7][i & 127] = W1[i];
    if (tid < 64) { b1s[tid] = b1[tid]; w2s[tid] = W2[tid]; }
    __syncthreads();

    float4 sc = *(const float4*)&stats[lane * 4];
    float4 sh = *(const float4*)&stats[128 + lane * 4];
    float bias2 = b2[0];
    float w2a = w2s[lane], w2b = w2s[lane + 32];
    float b1a = b1s[lane], b1b = b1s[lane + 32];

    const int ROWS = 8;
    int rbase = blockIdx.x * (8 * ROWS) + wid * ROWS;

    for (int rr = 0; rr < ROWS; rr++) {
        int r = rbase + rr;
        if (r >= M) return;
        float4 z = *(const float4*)&Zlast[(size_t)r * HID + lane * 4];
        float4 h = *(const float4*)&g_H0[(size_t)r * HID + lane * 4];
        z = xform4(z, sc, sh);
        z.x += h.x; z.y += h.y; z.z += h.z; z.w += h.w;
        *(float4*)&xsh[wid][lane * 4] = z;
        __syncwarp();

        float acc0 = 0.f, acc1 = 0.f;
        #pragma unroll
        for (int k = 0; k < 128; k += 4) {
            float4 xv = *(const float4*)&xsh[wid][k];
            float4 w0 = *(const float4*)&W1s[lane][k];
            float4 w1 = *(const float4*)&W1s[lane + 32][k];
            acc0 = fmaf(xv.x, w0.x, acc0); acc0 = fmaf(xv.y, w0.y, acc0);
            acc0 = fmaf(xv.z, w0.z, acc0); acc0 = fmaf(xv.w, w0.w, acc0);
            acc1 = fmaf(xv.x, w1.x, acc1); acc1 = fmaf(xv.y, w1.y, acc1);
            acc1 = fmaf(xv.z, w1.z, acc1); acc1 = fmaf(xv.w, w1.w, acc1);
        }
        float f0 = lrelu(acc0 + b1a);
        float f1 = lrelu(acc1 + b1b);
        float contrib = f0 * w2a + f1 * w2b;
        #pragma unroll
        for (int o = 16; o > 0; o >>= 1)
            contrib += __shfl_down_sync(0xffffffffu, contrib, o);
        if (lane == 0) out[r] = contrib + bias2;
        __syncwarp();
    }
}

// ============================ launch ========================================
extern "C" void kernel_launch(void* const* d_in, const int* in_sizes, int n_in,
                              void* d_out, int out_size)
{
    const float* x    = (const float*)d_in[0];
    const int*   ei   = (const int*)d_in[1];
    const float* W_in = (const float*)d_in[2];
    const float* b_in = (const float*)d_in[3];
    const float* Wl[3] = { (const float*)d_in[4], (const float*)d_in[7], (const float*)d_in[10] };
    const float* bl[3] = { (const float*)d_in[5], (const float*)d_in[8], (const float*)d_in[11] };
    const float* Wr[3] = { (const float*)d_in[6], (const float*)d_in[9], (const float*)d_in[12] };
    const float* gm[3] = { (const float*)d_in[13], (const float*)d_in[15], (const float*)d_in[17] };
    const float* be[3] = { (const float*)d_in[14], (const float*)d_in[16], (const float*)d_in[18] };
    const float* W_fc1 = (const float*)d_in[19];
    const float* b_fc1 = (const float*)d_in[20];
    const float* W_fc2 = (const float*)d_in[21];
    const float* b_fc2 = (const float*)d_in[22];
    float* out = (float*)d_out;

    int M = in_sizes[0] / HID;
    int E = in_sizes[1] / 2;
    const int* src = ei;
    const int* dst = ei + E;

    cudaFuncSetAttribute(gemm_proj, cudaFuncAttributeMaxDynamicSharedMemorySize,
                         SM_GEMM_TOTAL);
    cudaFuncSetAttribute(gemm_layer, cudaFuncAttributeMaxDynamicSharedMemorySize,
                         SM_GEMM_TOTAL);

    void *pH0v, *pZv, *pPartv, *pStatsv, *pDegv, *pAHv, *pALv, *pWv;
    cudaGetSymbolAddress(&pH0v, g_H0);
    cudaGetSymbolAddress(&pZv, g_Zb);
    cudaGetSymbolAddress(&pPartv, g_part);
    cudaGetSymbolAddress(&pStatsv, g_statsBuf);
    cudaGetSymbolAddress(&pDegv, g_deg);
    cudaGetSymbolAddress(&pAHv, g_AbfHi);
    cudaGetSymbolAddress(&pALv, g_AbfLo);
    cudaGetSymbolAddress(&pWv, g_Wbf);
    float* pH0 = (float*)pH0v;
    float* pZ0 = (float*)pZv;
    float* pZ1 = pZ0 + (size_t)NMAX * HID;
    float* pPart = (float*)pPartv;
    float* pStats0 = (float*)pStatsv;
    float* pStats1 = pStats0 + 256;
    uint16_t* pAH = (uint16_t*)pAHv;
    uint16_t* pAL = (uint16_t*)pALv;
    uint16_t* pW  = (uint16_t*)pWv;
    uint16_t* pWm[7];
    for (int i = 0; i < 7; i++) pWm[i] = pW + (size_t)i * 2 * 16384;

    int scanBlocks = (M + 1023) / 1024;
    int gemmGrid = (M + 127) / 128;
    int aggGrid = (M + 7) / 8;

    // ---- setup + CSR build; proj GEMM is the 4th launch (ncu target)
    cudaMemsetAsync(pDegv, 0, (size_t)M * sizeof(int));
    k_cvtW<<<dim3(32, 7), 256>>>(W_in, Wl[0], Wr[0], Wl[1], Wr[1], Wl[2], Wr[2]); // 1
    k_count<<<(E + 511) / 512, 512>>>(dst, E);                                     // 2
    k_scanA<<<scanBlocks, 1024>>>(M);                                              // 3
    gemm_proj<<<gemmGrid, 256, SM_GEMM_TOTAL>>>(x, pWm[0], b_in, pH0, M);          // 4 (profiled)
    k_scanB<<<1, 128>>>(scanBlocks);
    k_scanC<<<(M + 255) / 256, 256>>>(M);
    k_scatter<<<(E + 511) / 512, 512>>>(src, dst, E);

    // ---- layer 1 (agg over H0, no xform)
    k_agg<<<aggGrid, 256>>>(pH0, nullptr, 0, M);
    gemm_layer<<<gemmGrid, 256, SM_GEMM_TOTAL>>>(pAH, pAL, pH0, nullptr,
                                                 pWm[1], pWm[2], bl[0],
                                                 pZ0, pPart, M, 0);
    k_bnfinal<<<1, 1024>>>(gm[0], be[0], pStats0, M, gemmGrid);

    // ---- layer 2
    k_agg<<<aggGrid, 256>>>(pZ0, pStats0, 1, M);
    gemm_layer<<<gemmGrid, 256, SM_GEMM_TOTAL>>>(pAH, pAL, pZ0, pStats0,
                                                 pWm[3], pWm[4], bl[1],
                                                 pZ1, pPart, M, 1);
    k_bnfinal<<<1, 1024>>>(gm[1], be[1], pStats1, M, gemmGrid);

    // ---- layer 3
    k_agg<<<aggGrid, 256>>>(pZ1, pStats1, 1, M);
    gemm_layer<<<gemmGrid, 256, SM_GEMM_TOTAL>>>(pAH, pAL, pZ1, pStats1,
                                                 pWm[5], pWm[6], bl[2],
                                                 pZ0, pPart, M, 1);
    k_bnfinal<<<1, 1024>>>(gm[2], be[2], pStats0, M, gemmGrid);

    // ---- head
    k_fc<<<(M + 63) / 64, 256>>>(pZ0, pStats0, W_fc1, b_fc1, W_fc2, b_fc2, out, M);
}